// round 5
// baseline (speedup 1.0000x reference)
#include <cuda_runtime.h>
#include <cuda_fp16.h>
#include <cstdint>

// temporal_attention: x [B=2, T=8192, D=64] f32
//   S = X X^T ; y = softmax(S, dim=1) (column-normalized); out = (y @ X)^T
// Two-pass, shift a_j = ||x_j||^2. Legacy mma.sync fp16 (fp32 acc).
// R5: identical to R4 (M-tile 64, grid 256, 2 CTAs/SM) — R4 died to a
// container-level infra failure, not a kernel verdict; resubmitting.

#define T_DIM 8192
#define D_DIM 64
#define B_DIM 2
#define NCH   128
#define NIT   (T_DIM / NCH)   // 64
#define MTILE 64
#define LDX   72              // half stride for x-tiles
#define LDT   136             // half stride for [64 x 128] xT / P tiles

__device__ float  g_a[B_DIM * T_DIM];
__device__ float  g_r[B_DIM * T_DIM];
__device__ __half g_xh[B_DIM * T_DIM * D_DIM];
__device__ __half g_xth[B_DIM * D_DIM * T_DIM];

// ---------------- helpers ----------------
__device__ __forceinline__ uint32_t smem_u32(const void* p) {
    uint32_t a;
    asm("{ .reg .u64 t; cvta.to.shared.u64 t, %1; cvt.u32.u64 %0, t; }" : "=r"(a) : "l"(p));
    return a;
}
__device__ __forceinline__ void cpa16(uint32_t s, const void* g) {
    asm volatile("cp.async.cg.shared.global [%0], [%1], 16;" :: "r"(s), "l"(g));
}
#define CP_COMMIT() asm volatile("cp.async.commit_group;" ::: "memory")
#define CP_WAIT0()  asm volatile("cp.async.wait_group 0;" ::: "memory")

__device__ __forceinline__ void mma_f16(float* c, const uint32_t* a, const uint32_t* b) {
    asm volatile(
        "mma.sync.aligned.m16n8k16.row.col.f32.f16.f16.f32 "
        "{%0,%1,%2,%3}, {%4,%5,%6,%7}, {%8,%9}, {%0,%1,%2,%3};"
        : "+f"(c[0]), "+f"(c[1]), "+f"(c[2]), "+f"(c[3])
        : "r"(a[0]), "r"(a[1]), "r"(a[2]), "r"(a[3]), "r"(b[0]), "r"(b[1]));
}

// load [nrows x 64] half tile (row stride LDX) from g (row stride 64)
template <int NR>
__device__ __forceinline__ void ld_x(uint32_t dst, const __half* g, int tid) {
#pragma unroll
    for (int p = 0; p < NR / 32; p++) {
        int e = p * 2048 + tid * 8;
        int r = e >> 6, c = e & 63;
        cpa16(dst + (uint32_t)(r * (LDX * 2) + c * 2), g + (size_t)r * D_DIM + c);
    }
}
// load [64 x 128] half tile (row stride LDT) from gt (row stride T_DIM)
__device__ __forceinline__ void ld_xt(uint32_t dst, const __half* gt, int tid) {
#pragma unroll
    for (int p = 0; p < 4; p++) {
        int e = p * 2048 + tid * 8;
        int d = e >> 7, j = e & 127;
        cpa16(dst + (uint32_t)(d * (LDT * 2) + j * 2), gt + (size_t)d * T_DIM + j);
    }
}

// ---------------- k_prep: a_j + half conversion ----------------
__global__ void k_prep(const float* __restrict__ x) {
    const int tid = threadIdx.x;
    const int j = blockIdx.x * 16 + (tid >> 4);
    const int l = tid & 15;
    const float4 v = *reinterpret_cast<const float4*>(x + (size_t)j * D_DIM + l * 4);
    float s = v.x * v.x + v.y * v.y + v.z * v.z + v.w * v.w;
    s += __shfl_xor_sync(0xFFFFFFFFu, s, 8);
    s += __shfl_xor_sync(0xFFFFFFFFu, s, 4);
    s += __shfl_xor_sync(0xFFFFFFFFu, s, 2);
    s += __shfl_xor_sync(0xFFFFFFFFu, s, 1);
    if (l == 0) g_a[j] = s;
    __half2 h0 = __floats2half2_rn(v.x, v.y);
    __half2 h1 = __floats2half2_rn(v.z, v.w);
    uint2 pk;
    pk.x = *reinterpret_cast<uint32_t*>(&h0);
    pk.y = *reinterpret_cast<uint32_t*>(&h1);
    *reinterpret_cast<uint2*>(&g_xh[(size_t)j * D_DIM + l * 4]) = pk;
}

// ---------------- k_xt: g_xth[b][d][t] ----------------
__global__ void k_xt(const float* __restrict__ x) {
    __shared__ float tile[32][33];
    const int b = blockIdx.z, t0 = blockIdx.x * 32, d0 = blockIdx.y * 32;
    const int tx = threadIdx.x & 31, ty = threadIdx.x >> 5;
#pragma unroll
    for (int i = 0; i < 32; i += 8)
        tile[i + ty][tx] = x[((size_t)b * T_DIM + t0 + i + ty) * D_DIM + d0 + tx];
    __syncthreads();
#pragma unroll
    for (int i = 0; i < 32; i += 8)
        g_xth[((size_t)b * D_DIM + d0 + i + ty) * T_DIM + t0 + tx] =
            __float2half_rn(tile[tx][i + ty]);
}

// ---------------- k_stats (j-tile = 64 rows) ----------------
// smem: SA @1024 (9216) | SB0 @10240 (18432) | SB1 @28672 (18432) | end 47104
__global__ void __launch_bounds__(256, 2) k_stats() {
    extern __shared__ char sm[];
    const uint32_t smb = smem_u32(sm);
    const int tid = threadIdx.x, w = tid >> 5, lane = tid & 31;
    const int wm = w >> 2, wn = w & 3;
    const int gid = lane >> 2, tg = lane & 3;
    const int b = blockIdx.y, j0 = blockIdx.x * MTILE;
    const __half* xh = g_xh + (size_t)b * T_DIM * D_DIM;

    const uint32_t SA = 1024, SB0 = 10240, SB1 = 28672;
    const __half* pA = reinterpret_cast<const __half*>(sm + SA);

    ld_x<MTILE>(smb + SA, xh + (size_t)j0 * D_DIM, tid);
    ld_x<NCH>(smb + SB0, xh, tid);
    CP_COMMIT();
    CP_WAIT0();
    __syncthreads();

    float a_r[2][2];
#pragma unroll
    for (int mf = 0; mf < 2; mf++) {
        int r = wm * 32 + mf * 16 + gid;
        a_r[mf][0] = g_a[b * T_DIM + j0 + r];
        a_r[mf][1] = g_a[b * T_DIM + j0 + r + 8];
    }
    float rs[2][2];
#pragma unroll
    for (int mf = 0; mf < 2; mf++) { rs[mf][0] = 0.f; rs[mf][1] = 0.f; }

    for (int t = 0; t < NIT; t++) {
        const uint32_t SB  = (t & 1) ? SB1 : SB0;
        const uint32_t SBn = (t & 1) ? SB0 : SB1;
        if (t + 1 < NIT) {
            ld_x<NCH>(smb + SBn, xh + (size_t)(t + 1) * NCH * D_DIM, tid);
            CP_COMMIT();
        }
        const __half* pB = reinterpret_cast<const __half*>(sm + SB);

        float acc[2][4][4];
#pragma unroll
        for (int mf = 0; mf < 2; mf++)
#pragma unroll
            for (int nf = 0; nf < 4; nf++)
#pragma unroll
                for (int q = 0; q < 4; q++) acc[mf][nf][q] = 0.f;

#pragma unroll
        for (int kk = 0; kk < 4; kk++) {
            const int k0 = kk * 16;
            uint32_t A[2][4], Bf[4][2];
#pragma unroll
            for (int mf = 0; mf < 2; mf++) {
                int r = wm * 32 + mf * 16 + gid;
                A[mf][0] = *reinterpret_cast<const uint32_t*>(pA + r * LDX + k0 + 2 * tg);
                A[mf][1] = *reinterpret_cast<const uint32_t*>(pA + (r + 8) * LDX + k0 + 2 * tg);
                A[mf][2] = *reinterpret_cast<const uint32_t*>(pA + r * LDX + k0 + 8 + 2 * tg);
                A[mf][3] = *reinterpret_cast<const uint32_t*>(pA + (r + 8) * LDX + k0 + 8 + 2 * tg);
            }
#pragma unroll
            for (int nf = 0; nf < 4; nf++) {
                int cB = wn * 32 + nf * 8 + gid;
                Bf[nf][0] = *reinterpret_cast<const uint32_t*>(pB + cB * LDX + k0 + 2 * tg);
                Bf[nf][1] = *reinterpret_cast<const uint32_t*>(pB + cB * LDX + k0 + 8 + 2 * tg);
            }
#pragma unroll
            for (int mf = 0; mf < 2; mf++)
#pragma unroll
                for (int nf = 0; nf < 4; nf++)
                    mma_f16(acc[mf][nf], A[mf], Bf[nf]);
        }

#pragma unroll
        for (int mf = 0; mf < 2; mf++)
#pragma unroll
            for (int nf = 0; nf < 4; nf++) {
                rs[mf][0] += __expf(acc[mf][nf][0] - a_r[mf][0])
                           + __expf(acc[mf][nf][1] - a_r[mf][0]);
                rs[mf][1] += __expf(acc[mf][nf][2] - a_r[mf][1])
                           + __expf(acc[mf][nf][3] - a_r[mf][1]);
            }

        if (t + 1 < NIT) CP_WAIT0();
        __syncthreads();
    }

#pragma unroll
    for (int mf = 0; mf < 2; mf++)
#pragma unroll
        for (int h = 0; h < 2; h++) {
            float v = rs[mf][h];
            v += __shfl_xor_sync(0xFFFFFFFFu, v, 1);
            v += __shfl_xor_sync(0xFFFFFFFFu, v, 2);
            rs[mf][h] = v;
        }
    {
        float* red4 = reinterpret_cast<float*>(sm + SB0);  // tiles dead now
        __syncthreads();
        if (tg == 0) {
#pragma unroll
            for (int mf = 0; mf < 2; mf++) {
                int r = wm * 32 + mf * 16 + gid;
                red4[wn * MTILE + r]     = rs[mf][0];
                red4[wn * MTILE + r + 8] = rs[mf][1];
            }
        }
        __syncthreads();
        if (tid < MTILE) {
            float c = red4[tid] + red4[MTILE + tid] + red4[2 * MTILE + tid] + red4[3 * MTILE + tid];
            g_r[b * T_DIM + j0 + tid] = 1.0f / c;
        }
    }
}

// ---------------- k_out (i-tile = 64 rows) ----------------
// smem: sa0@0 sr0@512 sa1@1024 sr1@1536 | XI@2048 (9216) | XJ0@11264 (18432) |
//       XJ1@29696 | XJT0@48128 (17408) | XJT1@65536 | P@82944 (17408) | end 100352
__global__ void __launch_bounds__(256, 2) k_out(float* __restrict__ out) {
    extern __shared__ char sm[];
    const uint32_t smb = smem_u32(sm);
    const int tid = threadIdx.x, w = tid >> 5, lane = tid & 31;
    const int wm = w >> 2, wn = w & 3;
    const int gid = lane >> 2, tg = lane & 3;
    const int b = blockIdx.y, i0 = blockIdx.x * MTILE;
    const __half* xh  = g_xh  + (size_t)b * T_DIM * D_DIM;
    const __half* xth = g_xth + (size_t)b * D_DIM * T_DIM;
    float* ob = out + (size_t)b * D_DIM * T_DIM;

    const uint32_t XI = 2048, XJ0 = 11264, XJ1 = 29696, XJT0 = 48128, XJT1 = 65536, P = 82944;
    const __half* pXi = reinterpret_cast<const __half*>(sm + XI);
    __half* pP = reinterpret_cast<__half*>(sm + P);

    ld_x<MTILE>(smb + XI, xh + (size_t)i0 * D_DIM, tid);
    ld_x<NCH>(smb + XJ0, xh, tid);
    ld_xt(smb + XJT0, xth, tid);
    if (tid < 128) {
        reinterpret_cast<float*>(sm + 0)[tid]   = g_a[b * T_DIM + tid];
        reinterpret_cast<float*>(sm + 512)[tid] = g_r[b * T_DIM + tid];
    }
    CP_COMMIT();
    CP_WAIT0();
    __syncthreads();

    float accO[2][2][4];
#pragma unroll
    for (int mf = 0; mf < 2; mf++)
#pragma unroll
        for (int nf = 0; nf < 2; nf++)
#pragma unroll
            for (int q = 0; q < 4; q++) accO[mf][nf][q] = 0.f;

    for (int t = 0; t < NIT; t++) {
        const int buf = t & 1, nb = buf ^ 1;
        const __half* pXj = reinterpret_cast<const __half*>(sm + (buf ? XJ1 : XJ0));
        const __half* pT  = reinterpret_cast<const __half*>(sm + (buf ? XJT1 : XJT0));
        const float* sa = reinterpret_cast<const float*>(sm + (uint32_t)buf * 1024);
        const float* sr = reinterpret_cast<const float*>(sm + (uint32_t)buf * 1024 + 512);

        if (t + 1 < NIT) {
            ld_x<NCH>(smb + (nb ? XJ1 : XJ0), xh + (size_t)(t + 1) * NCH * D_DIM, tid);
            ld_xt(smb + (nb ? XJT1 : XJT0), xth + (size_t)(t + 1) * NCH, tid);
            CP_COMMIT();
            if (tid < 128) {
                reinterpret_cast<float*>(sm + (uint32_t)nb * 1024)[tid] =
                    g_a[b * T_DIM + (t + 1) * NCH + tid];
                reinterpret_cast<float*>(sm + (uint32_t)nb * 1024 + 512)[tid] =
                    g_r[b * T_DIM + (t + 1) * NCH + tid];
            }
        }

        // ---- S = Xi (64xK) * Xj^T (128 cols) ----
        float accS[2][4][4];
#pragma unroll
        for (int mf = 0; mf < 2; mf++)
#pragma unroll
            for (int nf = 0; nf < 4; nf++)
#pragma unroll
                for (int q = 0; q < 4; q++) accS[mf][nf][q] = 0.f;

#pragma unroll
        for (int kk = 0; kk < 4; kk++) {
            const int k0 = kk * 16;
            uint32_t A[2][4], Bf[4][2];
#pragma unroll
            for (int mf = 0; mf < 2; mf++) {
                int r = wm * 32 + mf * 16 + gid;
                A[mf][0] = *reinterpret_cast<const uint32_t*>(pXi + r * LDX + k0 + 2 * tg);
                A[mf][1] = *reinterpret_cast<const uint32_t*>(pXi + (r + 8) * LDX + k0 + 2 * tg);
                A[mf][2] = *reinterpret_cast<const uint32_t*>(pXi + r * LDX + k0 + 8 + 2 * tg);
                A[mf][3] = *reinterpret_cast<const uint32_t*>(pXi + (r + 8) * LDX + k0 + 8 + 2 * tg);
            }
#pragma unroll
            for (int nf = 0; nf < 4; nf++) {
                int cB = wn * 32 + nf * 8 + gid;
                Bf[nf][0] = *reinterpret_cast<const uint32_t*>(pXj + cB * LDX + k0 + 2 * tg);
                Bf[nf][1] = *reinterpret_cast<const uint32_t*>(pXj + cB * LDX + k0 + 8 + 2 * tg);
            }
#pragma unroll
            for (int mf = 0; mf < 2; mf++)
#pragma unroll
                for (int nf = 0; nf < 4; nf++)
                    mma_f16(accS[mf][nf], A[mf], Bf[nf]);
        }

        // ---- P = exp(S - a_j) * r_j -> fp16 SMEM ----
#pragma unroll
        for (int nf = 0; nf < 4; nf++) {
            int c0 = wn * 32 + nf * 8 + 2 * tg;
            float a0 = sa[c0], a1 = sa[c0 + 1];
            float r0v = sr[c0], r1v = sr[c0 + 1];
#pragma unroll
            for (int mf = 0; mf < 2; mf++) {
                int r = wm * 32 + mf * 16 + gid;
                __half2 p01 = __floats2half2_rn(__expf(accS[mf][nf][0] - a0) * r0v,
                                                __expf(accS[mf][nf][1] - a1) * r1v);
                __half2 p23 = __floats2half2_rn(__expf(accS[mf][nf][2] - a0) * r0v,
                                                __expf(accS[mf][nf][3] - a1) * r1v);
                *reinterpret_cast<__half2*>(pP + r * LDT + c0)       = p01;
                *reinterpret_cast<__half2*>(pP + (r + 8) * LDT + c0) = p23;
            }
        }
        __syncthreads();

        // ---- O += P (64x128) * XjT ----
#pragma unroll
        for (int kk = 0; kk < 8; kk++) {
            const int k0 = kk * 16;
            uint32_t A[2][4], Bf[2][2];
#pragma unroll
            for (int mf = 0; mf < 2; mf++) {
                int r = wm * 32 + mf * 16 + gid;
                A[mf][0] = *reinterpret_cast<const uint32_t*>(pP + r * LDT + k0 + 2 * tg);
                A[mf][1] = *reinterpret_cast<const uint32_t*>(pP + (r + 8) * LDT + k0 + 2 * tg);
                A[mf][2] = *reinterpret_cast<const uint32_t*>(pP + r * LDT + k0 + 8 + 2 * tg);
                A[mf][3] = *reinterpret_cast<const uint32_t*>(pP + (r + 8) * LDT + k0 + 8 + 2 * tg);
            }
#pragma unroll
            for (int nf = 0; nf < 2; nf++) {
                int cB = wn * 16 + nf * 8 + gid;
                Bf[nf][0] = *reinterpret_cast<const uint32_t*>(pT + cB * LDT + k0 + 2 * tg);
                Bf[nf][1] = *reinterpret_cast<const uint32_t*>(pT + cB * LDT + k0 + 8 + 2 * tg);
            }
#pragma unroll
            for (int mf = 0; mf < 2; mf++)
#pragma unroll
                for (int nf = 0; nf < 2; nf++)
                    mma_f16(accO[mf][nf], A[mf], Bf[nf]);
        }

        if (t + 1 < NIT) CP_WAIT0();
        __syncthreads();
    }

    // ---- store transposed: out[b][d][i] ----
#pragma unroll
    for (int mf = 0; mf < 2; mf++)
#pragma unroll
        for (int nf = 0; nf < 2; nf++) {
            int r = i0 + wm * 32 + mf * 16 + gid;
            int c = wn * 16 + nf * 8 + 2 * tg;
            ob[(size_t)c * T_DIM + r]           = accO[mf][nf][0];
            ob[(size_t)(c + 1) * T_DIM + r]     = accO[mf][nf][1];
            ob[(size_t)c * T_DIM + r + 8]       = accO[mf][nf][2];
            ob[(size_t)(c + 1) * T_DIM + r + 8] = accO[mf][nf][3];
        }
}

// ---------------------------------------------------------------------------
extern "C" void kernel_launch(void* const* d_in, const int* in_sizes, int n_in,
                              void* d_out, int out_size) {
    const float* x = (const float*)d_in[0];
    float* out = (float*)d_out;

    const int smem_stats = 47104;
    const int smem_out   = 100352;
    cudaFuncSetAttribute(k_stats, cudaFuncAttributeMaxDynamicSharedMemorySize, smem_stats);
    cudaFuncSetAttribute(k_out,   cudaFuncAttributeMaxDynamicSharedMemorySize, smem_out);

    k_prep<<<(B_DIM * T_DIM) / 16, 256>>>(x);
    k_xt<<<dim3(T_DIM / 32, D_DIM / 32, B_DIM), 256>>>(x);
    k_stats<<<dim3(T_DIM / MTILE, B_DIM), 256, smem_stats>>>();
    k_out<<<dim3(T_DIM / MTILE, B_DIM), 256, smem_out>>>(out);
}

// round 6
// speedup vs baseline: 1.1221x; 1.1221x over previous
#include <cuda_runtime.h>
#include <cuda_fp16.h>
#include <cstdint>

// temporal_attention: x [B=2, T=8192, D=64] f32
//   S = X X^T ; y = softmax(S, dim=1) (column-normalized); out = (y @ X)^T
// R6: materialize E = fp16(exp(s_ij - a_j)) (in (0,1], no overflow) to gmem in
// pass 1; pass 2 becomes a pure streaming GEMM O = E @ (r*X). Removes the
// duplicated S-GEMM + exp from pass 2; trades it for 256MB write + 256MB read
// on an otherwise idle (0.3%) HBM.
//   k_prep : a_j + g_xh = half(x)
//   k_stats: E tiles -> g_E[i][j] (transposed store), c_j -> g_r = 1/c
//   k_vt   : g_vt[d][t] = half(r_t * x[t][d])
//   k_out2 : O[i][d] = sum_j E[i][j] * Vt[d][j]   (pure fp16 mma GEMM)

#define T_DIM 8192
#define D_DIM 64
#define B_DIM 2
#define NCH   128
#define NIT   (T_DIM / NCH)   // 64
#define LDX   72              // half stride for x-tiles
#define LDE   136             // half stride for 128x128 E / 64x128 Vt tiles

__device__ float  g_a[B_DIM * T_DIM];
__device__ float  g_r[B_DIM * T_DIM];
__device__ __half g_xh[B_DIM * T_DIM * D_DIM];
__device__ __half g_vt[B_DIM * D_DIM * T_DIM];
__device__ __half g_E[(size_t)B_DIM * T_DIM * T_DIM];   // 268 MB

// ---------------- helpers ----------------
__device__ __forceinline__ uint32_t smem_u32(const void* p) {
    uint32_t a;
    asm("{ .reg .u64 t; cvta.to.shared.u64 t, %1; cvt.u32.u64 %0, t; }" : "=r"(a) : "l"(p));
    return a;
}
__device__ __forceinline__ void cpa16(uint32_t s, const void* g) {
    asm volatile("cp.async.cg.shared.global [%0], [%1], 16;" :: "r"(s), "l"(g));
}
#define CP_COMMIT() asm volatile("cp.async.commit_group;" ::: "memory")
#define CP_WAIT0()  asm volatile("cp.async.wait_group 0;" ::: "memory")

__device__ __forceinline__ void mma_f16(float* c, const uint32_t* a, const uint32_t* b) {
    asm volatile(
        "mma.sync.aligned.m16n8k16.row.col.f32.f16.f16.f32 "
        "{%0,%1,%2,%3}, {%4,%5,%6,%7}, {%8,%9}, {%0,%1,%2,%3};"
        : "+f"(c[0]), "+f"(c[1]), "+f"(c[2]), "+f"(c[3])
        : "r"(a[0]), "r"(a[1]), "r"(a[2]), "r"(a[3]), "r"(b[0]), "r"(b[1]));
}

// load [128 x 64] half tile (row stride LDX) from g (row stride 64)
__device__ __forceinline__ void ld_x(uint32_t dst, const __half* g, int tid) {
#pragma unroll
    for (int p = 0; p < 4; p++) {
        int e = p * 2048 + tid * 8;
        int r = e >> 6, c = e & 63;
        cpa16(dst + (uint32_t)(r * (LDX * 2) + c * 2), g + (size_t)r * D_DIM + c);
    }
}
// load [128 x 128] half tile (row stride LDE) from g (row stride T_DIM)
__device__ __forceinline__ void ld_e(uint32_t dst, const __half* g, int tid) {
#pragma unroll
    for (int p = 0; p < 8; p++) {
        int e = p * 2048 + tid * 8;
        int r = e >> 7, c = e & 127;
        cpa16(dst + (uint32_t)(r * (LDE * 2) + c * 2), g + (size_t)r * T_DIM + c);
    }
}
// load [64 x 128] half tile (row stride LDE) from g (row stride T_DIM)
__device__ __forceinline__ void ld_vt(uint32_t dst, const __half* g, int tid) {
#pragma unroll
    for (int p = 0; p < 4; p++) {
        int e = p * 2048 + tid * 8;
        int d = e >> 7, j = e & 127;
        cpa16(dst + (uint32_t)(d * (LDE * 2) + j * 2), g + (size_t)d * T_DIM + j);
    }
}

// ---------------- k_prep: a_j + half conversion ----------------
__global__ void k_prep(const float* __restrict__ x) {
    const int tid = threadIdx.x;
    const int j = blockIdx.x * 16 + (tid >> 4);
    const int l = tid & 15;
    const float4 v = *reinterpret_cast<const float4*>(x + (size_t)j * D_DIM + l * 4);
    float s = v.x * v.x + v.y * v.y + v.z * v.z + v.w * v.w;
    s += __shfl_xor_sync(0xFFFFFFFFu, s, 8);
    s += __shfl_xor_sync(0xFFFFFFFFu, s, 4);
    s += __shfl_xor_sync(0xFFFFFFFFu, s, 2);
    s += __shfl_xor_sync(0xFFFFFFFFu, s, 1);
    if (l == 0) g_a[j] = s;
    __half2 h0 = __floats2half2_rn(v.x, v.y);
    __half2 h1 = __floats2half2_rn(v.z, v.w);
    uint2 pk;
    pk.x = *reinterpret_cast<uint32_t*>(&h0);
    pk.y = *reinterpret_cast<uint32_t*>(&h1);
    *reinterpret_cast<uint2*>(&g_xh[(size_t)j * D_DIM + l * 4]) = pk;
}

// ---------------- k_vt: g_vt[b][d][t] = half(r_t * x[t][d]) ----------------
__global__ void k_vt(const float* __restrict__ x) {
    __shared__ float tile[32][33];
    const int b = blockIdx.z, t0 = blockIdx.x * 32, d0 = blockIdx.y * 32;
    const int tx = threadIdx.x & 31, ty = threadIdx.x >> 5;
#pragma unroll
    for (int i = 0; i < 32; i += 8)
        tile[i + ty][tx] = x[((size_t)b * T_DIM + t0 + i + ty) * D_DIM + d0 + tx]
                         * g_r[b * T_DIM + t0 + i + ty];
    __syncthreads();
#pragma unroll
    for (int i = 0; i < 32; i += 8)
        g_vt[((size_t)b * D_DIM + d0 + i + ty) * T_DIM + t0 + tx] =
            __float2half_rn(tile[tx][i + ty]);
}

// ---------------- k_stats (j-tile = 128): E tiles + column sums ----------------
// smem: SA @1024 (18432) | SB0 @19456 (18432) | SB1 @37888 (18432) |
//       sEt @56320 (128*LDE*2 = 34816) -> end 91136
__global__ void __launch_bounds__(256, 1) k_stats() {
    extern __shared__ char sm[];
    const uint32_t smb = smem_u32(sm);
    const int tid = threadIdx.x, w = tid >> 5, lane = tid & 31;
    const int wm = w >> 2, wn = w & 3;
    const int gid = lane >> 2, tg = lane & 3;
    const int b = blockIdx.y, j0 = blockIdx.x * 128;
    const __half* xh = g_xh + (size_t)b * T_DIM * D_DIM;
    __half* Eb = g_E + (size_t)b * T_DIM * T_DIM;

    const uint32_t SA = 1024, SB0 = 19456, SB1 = 37888, SET = 56320;
    const __half* pA = reinterpret_cast<const __half*>(sm + SA);
    __half* pEt = reinterpret_cast<__half*>(sm + SET);

    ld_x(smb + SA, xh + (size_t)j0 * D_DIM, tid);
    ld_x(smb + SB0, xh, tid);
    CP_COMMIT();
    CP_WAIT0();
    __syncthreads();

    float a_r[4][2];
#pragma unroll
    for (int mf = 0; mf < 4; mf++) {
        int r = wm * 64 + mf * 16 + gid;
        a_r[mf][0] = g_a[b * T_DIM + j0 + r];
        a_r[mf][1] = g_a[b * T_DIM + j0 + r + 8];
    }
    float rs[4][2];
#pragma unroll
    for (int mf = 0; mf < 4; mf++) { rs[mf][0] = 0.f; rs[mf][1] = 0.f; }

    for (int t = 0; t < NIT; t++) {
        const uint32_t SB  = (t & 1) ? SB1 : SB0;
        const uint32_t SBn = (t & 1) ? SB0 : SB1;
        if (t + 1 < NIT) {
            ld_x(smb + SBn, xh + (size_t)(t + 1) * NCH * D_DIM, tid);
            CP_COMMIT();
        }
        const __half* pB = reinterpret_cast<const __half*>(sm + SB);

        float acc[4][4][4];
#pragma unroll
        for (int mf = 0; mf < 4; mf++)
#pragma unroll
            for (int nf = 0; nf < 4; nf++)
#pragma unroll
                for (int q = 0; q < 4; q++) acc[mf][nf][q] = 0.f;

#pragma unroll
        for (int kk = 0; kk < 4; kk++) {
            const int k0 = kk * 16;
            uint32_t A[4][4], Bf[4][2];
#pragma unroll
            for (int mf = 0; mf < 4; mf++) {
                int r = wm * 64 + mf * 16 + gid;
                A[mf][0] = *reinterpret_cast<const uint32_t*>(pA + r * LDX + k0 + 2 * tg);
                A[mf][1] = *reinterpret_cast<const uint32_t*>(pA + (r + 8) * LDX + k0 + 2 * tg);
                A[mf][2] = *reinterpret_cast<const uint32_t*>(pA + r * LDX + k0 + 8 + 2 * tg);
                A[mf][3] = *reinterpret_cast<const uint32_t*>(pA + (r + 8) * LDX + k0 + 8 + 2 * tg);
            }
#pragma unroll
            for (int nf = 0; nf < 4; nf++) {
                int cB = wn * 32 + nf * 8 + gid;
                Bf[nf][0] = *reinterpret_cast<const uint32_t*>(pB + cB * LDX + k0 + 2 * tg);
                Bf[nf][1] = *reinterpret_cast<const uint32_t*>(pB + cB * LDX + k0 + 8 + 2 * tg);
            }
#pragma unroll
            for (int mf = 0; mf < 4; mf++)
#pragma unroll
                for (int nf = 0; nf < 4; nf++)
                    mma_f16(acc[mf][nf], A[mf], Bf[nf]);
        }

        // E = fp16(exp(S - a_row)); accumulate row sums of the ROUNDED values;
        // store transposed into sEt[i_local][j_local]
#pragma unroll
        for (int mf = 0; mf < 4; mf++) {
            int r = wm * 64 + mf * 16 + gid;
#pragma unroll
            for (int nf = 0; nf < 4; nf++) {
                int c0 = wn * 32 + nf * 8 + 2 * tg;
                __half h0 = __float2half_rn(__expf(acc[mf][nf][0] - a_r[mf][0]));
                __half h1 = __float2half_rn(__expf(acc[mf][nf][1] - a_r[mf][0]));
                __half h2 = __float2half_rn(__expf(acc[mf][nf][2] - a_r[mf][1]));
                __half h3 = __float2half_rn(__expf(acc[mf][nf][3] - a_r[mf][1]));
                rs[mf][0] += __half2float(h0) + __half2float(h1);
                rs[mf][1] += __half2float(h2) + __half2float(h3);
                pEt[c0 * LDE + r]           = h0;
                pEt[(c0 + 1) * LDE + r]     = h1;
                pEt[c0 * LDE + r + 8]       = h2;
                pEt[(c0 + 1) * LDE + r + 8] = h3;
            }
        }
        __syncthreads();  // sEt complete

        // drain sEt -> gmem E[i][j] (coalesced 16B stores)
        const int i0 = t * NCH;
#pragma unroll
        for (int p = 0; p < 8; p++) {
            int e = p * 2048 + tid * 8;
            int il = e >> 7, jl = e & 127;
            uint4 v = *reinterpret_cast<const uint4*>(pEt + il * LDE + jl);
            *reinterpret_cast<uint4*>(Eb + (size_t)(i0 + il) * T_DIM + j0 + jl) = v;
        }
        if (t + 1 < NIT) CP_WAIT0();
        __syncthreads();  // sEt free for next iter; SB swap safe
    }

    // reduce rs over quad lanes then across the 4 n-warps
#pragma unroll
    for (int mf = 0; mf < 4; mf++)
#pragma unroll
        for (int h = 0; h < 2; h++) {
            float v = rs[mf][h];
            v += __shfl_xor_sync(0xFFFFFFFFu, v, 1);
            v += __shfl_xor_sync(0xFFFFFFFFu, v, 2);
            rs[mf][h] = v;
        }
    {
        float* red4 = reinterpret_cast<float*>(sm + SET);  // sEt dead now
        if (tg == 0) {
#pragma unroll
            for (int mf = 0; mf < 4; mf++) {
                int r = wm * 64 + mf * 16 + gid;
                red4[wn * 128 + r]     = rs[mf][0];
                red4[wn * 128 + r + 8] = rs[mf][1];
            }
        }
        __syncthreads();
        if (tid < 128) {
            float c = red4[tid] + red4[128 + tid] + red4[256 + tid] + red4[384 + tid];
            g_r[b * T_DIM + j0 + tid] = 1.0f / c;
        }
    }
}

// ---------------- k_out2: pure GEMM O[i][d] = sum_j E[i][j] Vt[d][j] ----------------
// smem: VT0 @0 (17408) | VT1 @17408 | E0 @34816 (34816) | E1 @69632 -> end 104448
__global__ void __launch_bounds__(256, 1) k_out2(float* __restrict__ out) {
    extern __shared__ char sm[];
    const uint32_t smb = smem_u32(sm);
    const int tid = threadIdx.x, w = tid >> 5, lane = tid & 31;
    const int wm = w >> 2, wn = w & 3;
    const int gid = lane >> 2, tg = lane & 3;
    const int b = blockIdx.y, i0 = blockIdx.x * 128;
    const __half* vt = g_vt + (size_t)b * D_DIM * T_DIM;
    const __half* Eb = g_E + (size_t)b * T_DIM * T_DIM + (size_t)i0 * T_DIM;
    float* ob = out + (size_t)b * D_DIM * T_DIM;

    const uint32_t VT0 = 0, VT1 = 17408, E0 = 34816, E1 = 69632;

    ld_vt(smb + VT0, vt, tid);
    ld_e(smb + E0, Eb, tid);
    CP_COMMIT();
    CP_WAIT0();
    __syncthreads();

    float accO[4][2][4];
#pragma unroll
    for (int mf = 0; mf < 4; mf++)
#pragma unroll
        for (int nf = 0; nf < 2; nf++)
#pragma unroll
            for (int q = 0; q < 4; q++) accO[mf][nf][q] = 0.f;

    for (int t = 0; t < NIT; t++) {
        const int buf = t & 1, nb = buf ^ 1;
        const __half* pE = reinterpret_cast<const __half*>(sm + (buf ? E1 : E0));
        const __half* pT = reinterpret_cast<const __half*>(sm + (buf ? VT1 : VT0));

        if (t + 1 < NIT) {
            ld_vt(smb + (nb ? VT1 : VT0), vt + (size_t)(t + 1) * NCH, tid);
            ld_e(smb + (nb ? E1 : E0), Eb + (size_t)(t + 1) * NCH, tid);
            CP_COMMIT();
        }

#pragma unroll
        for (int kk = 0; kk < 8; kk++) {
            const int k0 = kk * 16;
            uint32_t A[4][4], Bf[2][2];
#pragma unroll
            for (int mf = 0; mf < 4; mf++) {
                int r = wm * 64 + mf * 16 + gid;
                A[mf][0] = *reinterpret_cast<const uint32_t*>(pE + r * LDE + k0 + 2 * tg);
                A[mf][1] = *reinterpret_cast<const uint32_t*>(pE + (r + 8) * LDE + k0 + 2 * tg);
                A[mf][2] = *reinterpret_cast<const uint32_t*>(pE + r * LDE + k0 + 8 + 2 * tg);
                A[mf][3] = *reinterpret_cast<const uint32_t*>(pE + (r + 8) * LDE + k0 + 8 + 2 * tg);
            }
#pragma unroll
            for (int nf = 0; nf < 2; nf++) {
                int cB = wn * 16 + nf * 8 + gid;
                Bf[nf][0] = *reinterpret_cast<const uint32_t*>(pT + cB * LDE + k0 + 2 * tg);
                Bf[nf][1] = *reinterpret_cast<const uint32_t*>(pT + cB * LDE + k0 + 8 + 2 * tg);
            }
#pragma unroll
            for (int mf = 0; mf < 4; mf++)
#pragma unroll
                for (int nf = 0; nf < 2; nf++)
                    mma_f16(accO[mf][nf], A[mf], Bf[nf]);
        }

        if (t + 1 < NIT) CP_WAIT0();
        __syncthreads();
    }

    // store transposed: out[b][d][i]
#pragma unroll
    for (int mf = 0; mf < 4; mf++)
#pragma unroll
        for (int nf = 0; nf < 2; nf++) {
            int r = i0 + wm * 64 + mf * 16 + gid;
            int c = wn * 16 + nf * 8 + 2 * tg;
            ob[(size_t)c * T_DIM + r]           = accO[mf][nf][0];
            ob[(size_t)(c + 1) * T_DIM + r]     = accO[mf][nf][1];
            ob[(size_t)c * T_DIM + r + 8]       = accO[mf][nf][2];
            ob[(size_t)(c + 1) * T_DIM + r + 8] = accO[mf][nf][3];
        }
}

// ---------------------------------------------------------------------------
extern "C" void kernel_launch(void* const* d_in, const int* in_sizes, int n_in,
                              void* d_out, int out_size) {
    const float* x = (const float*)d_in[0];
    float* out = (float*)d_out;

    const int smem_stats = 91136;
    const int smem_out   = 104448;
    cudaFuncSetAttribute(k_stats, cudaFuncAttributeMaxDynamicSharedMemorySize, smem_stats);
    cudaFuncSetAttribute(k_out2,  cudaFuncAttributeMaxDynamicSharedMemorySize, smem_out);

    k_prep<<<(B_DIM * T_DIM) / 16, 256>>>(x);
    k_stats<<<dim3(T_DIM / NCH, B_DIM), 256, smem_stats>>>();
    k_vt<<<dim3(T_DIM / 32, D_DIM / 32, B_DIM), 256>>>(x);
    k_out2<<<dim3(T_DIM / NCH, B_DIM), 256, smem_out>>>(out);
}

// round 7
// speedup vs baseline: 1.2558x; 1.1192x over previous
#include <cuda_runtime.h>
#include <cuda_fp16.h>
#include <cstdint>

// temporal_attention: x [B=2, T=8192, D=64] f32
//   S = X X^T ; y = softmax(S, dim=1) (column-normalized); out = (y @ X)^T
// R7: E-materialization (R6) with
//   - k_stats operand swap: acc holds E[i][j,j+1] -> direct half2 STG, no SMEM
//     transpose; column sums via in-register over-i accumulation.
//   - 3-stage cp.async pipelines (depth-2 prefetch) in k_stats and k_out2.
//   k_prep : a_j + g_xh = half(x)
//   k_stats: E[i][j] tiles -> gmem, c_j -> g_r = 1/c
//   k_vt   : g_vt[d][t] = half(r_t * x[t][d])
//   k_out2 : O[i][d] = sum_j E[i][j] * Vt[d][j]   (pure fp16 mma GEMM)

#define T_DIM 8192
#define D_DIM 64
#define B_DIM 2
#define NCH   128
#define NIT   (T_DIM / NCH)   // 64
#define LDX   72              // half stride for [128 x 64] x-tiles
#define LDE   136             // half stride for [128|64 x 128] E / Vt tiles

__device__ float  g_a[B_DIM * T_DIM];
__device__ float  g_r[B_DIM * T_DIM];
__device__ __half g_xh[B_DIM * T_DIM * D_DIM];
__device__ __half g_vt[B_DIM * D_DIM * T_DIM];
__device__ __half g_E[(size_t)B_DIM * T_DIM * T_DIM];   // 268 MB

// ---------------- helpers ----------------
__device__ __forceinline__ uint32_t smem_u32(const void* p) {
    uint32_t a;
    asm("{ .reg .u64 t; cvta.to.shared.u64 t, %1; cvt.u32.u64 %0, t; }" : "=r"(a) : "l"(p));
    return a;
}
__device__ __forceinline__ void cpa16(uint32_t s, const void* g) {
    asm volatile("cp.async.cg.shared.global [%0], [%1], 16;" :: "r"(s), "l"(g));
}
#define CP_COMMIT() asm volatile("cp.async.commit_group;" ::: "memory")
#define CP_WAIT0()  asm volatile("cp.async.wait_group 0;" ::: "memory")
#define CP_WAIT1()  asm volatile("cp.async.wait_group 1;" ::: "memory")

__device__ __forceinline__ void mma_f16(float* c, const uint32_t* a, const uint32_t* b) {
    asm volatile(
        "mma.sync.aligned.m16n8k16.row.col.f32.f16.f16.f32 "
        "{%0,%1,%2,%3}, {%4,%5,%6,%7}, {%8,%9}, {%0,%1,%2,%3};"
        : "+f"(c[0]), "+f"(c[1]), "+f"(c[2]), "+f"(c[3])
        : "r"(a[0]), "r"(a[1]), "r"(a[2]), "r"(a[3]), "r"(b[0]), "r"(b[1]));
}

// load [128 x 64] half tile (row stride LDX) from g (row stride 64)
__device__ __forceinline__ void ld_x(uint32_t dst, const __half* g, int tid) {
#pragma unroll
    for (int p = 0; p < 4; p++) {
        int e = p * 2048 + tid * 8;
        int r = e >> 6, c = e & 63;
        cpa16(dst + (uint32_t)(r * (LDX * 2) + c * 2), g + (size_t)r * D_DIM + c);
    }
}
// load [128 x 128] half tile (row stride LDE) from g (row stride T_DIM)
__device__ __forceinline__ void ld_e(uint32_t dst, const __half* g, int tid) {
#pragma unroll
    for (int p = 0; p < 8; p++) {
        int e = p * 2048 + tid * 8;
        int r = e >> 7, c = e & 127;
        cpa16(dst + (uint32_t)(r * (LDE * 2) + c * 2), g + (size_t)r * T_DIM + c);
    }
}
// load [64 x 128] half tile (row stride LDE) from g (row stride T_DIM)
__device__ __forceinline__ void ld_vt(uint32_t dst, const __half* g, int tid) {
#pragma unroll
    for (int p = 0; p < 4; p++) {
        int e = p * 2048 + tid * 8;
        int d = e >> 7, j = e & 127;
        cpa16(dst + (uint32_t)(d * (LDE * 2) + j * 2), g + (size_t)d * T_DIM + j);
    }
}

// ---------------- k_prep: a_j + half conversion ----------------
__global__ void k_prep(const float* __restrict__ x) {
    const int tid = threadIdx.x;
    const int j = blockIdx.x * 16 + (tid >> 4);
    const int l = tid & 15;
    const float4 v = *reinterpret_cast<const float4*>(x + (size_t)j * D_DIM + l * 4);
    float s = v.x * v.x + v.y * v.y + v.z * v.z + v.w * v.w;
    s += __shfl_xor_sync(0xFFFFFFFFu, s, 8);
    s += __shfl_xor_sync(0xFFFFFFFFu, s, 4);
    s += __shfl_xor_sync(0xFFFFFFFFu, s, 2);
    s += __shfl_xor_sync(0xFFFFFFFFu, s, 1);
    if (l == 0) g_a[j] = s;
    __half2 h0 = __floats2half2_rn(v.x, v.y);
    __half2 h1 = __floats2half2_rn(v.z, v.w);
    uint2 pk;
    pk.x = *reinterpret_cast<uint32_t*>(&h0);
    pk.y = *reinterpret_cast<uint32_t*>(&h1);
    *reinterpret_cast<uint2*>(&g_xh[(size_t)j * D_DIM + l * 4]) = pk;
}

// ---------------- k_vt: g_vt[b][d][t] = half(r_t * x[t][d]) ----------------
__global__ void k_vt(const float* __restrict__ x) {
    __shared__ float tile[32][33];
    const int b = blockIdx.z, t0 = blockIdx.x * 32, d0 = blockIdx.y * 32;
    const int tx = threadIdx.x & 31, ty = threadIdx.x >> 5;
#pragma unroll
    for (int i = 0; i < 32; i += 8)
        tile[i + ty][tx] = x[((size_t)b * T_DIM + t0 + i + ty) * D_DIM + d0 + tx]
                         * g_r[b * T_DIM + t0 + i + ty];
    __syncthreads();
#pragma unroll
    for (int i = 0; i < 32; i += 8)
        g_vt[((size_t)b * D_DIM + d0 + i + ty) * T_DIM + t0 + tx] =
            __float2half_rn(tile[tx][i + ty]);
}

// ---------------- k_stats (fixed j-tile = 128 cols, stream i-chunks) --------
// A = Xi chunk (rows i, streamed), B = Xj tile (cols j, fixed).
// acc[m=i][n=j] -> E[i][j], adjacent j in fragment -> direct half2 STG.
// smem: SA @0 (18432) | S0 @18432 | S1 @36864 | S2 @55296 -> end 73728
__global__ void __launch_bounds__(256, 1) k_stats() {
    extern __shared__ char sm[];
    const uint32_t smb = smem_u32(sm);
    const int tid = threadIdx.x, w = tid >> 5, lane = tid & 31;
    const int wm = w >> 2, wn = w & 3;
    const int gid = lane >> 2, tg = lane & 3;
    const int b = blockIdx.y, j0 = blockIdx.x * 128;
    const __half* xh = g_xh + (size_t)b * T_DIM * D_DIM;
    __half* Eb = g_E + (size_t)b * T_DIM * T_DIM;

    const uint32_t SA = 0;
    const uint32_t SBUF[3] = {18432, 36864, 55296};
    const __half* pA = reinterpret_cast<const __half*>(sm + SA);

    // prologue: group0 = SA + chunk0, group1 = chunk1
    ld_x(smb + SA, xh + (size_t)j0 * D_DIM, tid);       // Xj tile (B operand)
    ld_x(smb + SBUF[0], xh, tid);                       // Xi chunk 0
    CP_COMMIT();
    ld_x(smb + SBUF[1], xh + (size_t)NCH * D_DIM, tid); // Xi chunk 1
    CP_COMMIT();

    // per-thread column shifts a_j for owned columns
    float a_c[4][2];
#pragma unroll
    for (int nf = 0; nf < 4; nf++) {
        int c0 = wn * 32 + nf * 8 + 2 * tg;
        a_c[nf][0] = g_a[b * T_DIM + j0 + c0];
        a_c[nf][1] = g_a[b * T_DIM + j0 + c0 + 1];
    }
    float rs[4][2];
#pragma unroll
    for (int nf = 0; nf < 4; nf++) { rs[nf][0] = 0.f; rs[nf][1] = 0.f; }

    // wait for group0 (SA + chunk0), then hoist fixed B fragments
    CP_WAIT1();
    __syncthreads();
    uint32_t Bf[4][4][2];   // [kk][nf][2]
#pragma unroll
    for (int kk = 0; kk < 4; kk++) {
        const int k0 = kk * 16;
#pragma unroll
        for (int nf = 0; nf < 4; nf++) {
            int cB = wn * 32 + nf * 8 + gid;
            Bf[kk][nf][0] = *reinterpret_cast<const uint32_t*>(pA + cB * LDX + k0 + 2 * tg);
            Bf[kk][nf][1] = *reinterpret_cast<const uint32_t*>(pA + cB * LDX + k0 + 8 + 2 * tg);
        }
    }

    for (int t = 0; t < NIT; t++) {
        if (t > 0) {                // group t must be complete
            if (t + 1 < NIT) CP_WAIT1(); else CP_WAIT0();
            __syncthreads();        // all warps done with buf[(t-1)%3]
        }
        if (t + 2 < NIT) {
            ld_x(smb + SBUF[(t + 2) % 3], xh + (size_t)(t + 2) * NCH * D_DIM, tid);
            CP_COMMIT();
        }
        const __half* pS = reinterpret_cast<const __half*>(sm + SBUF[t % 3]);

        float acc[4][4][4];
#pragma unroll
        for (int mf = 0; mf < 4; mf++)
#pragma unroll
            for (int nf = 0; nf < 4; nf++)
#pragma unroll
                for (int q = 0; q < 4; q++) acc[mf][nf][q] = 0.f;

#pragma unroll
        for (int kk = 0; kk < 4; kk++) {
            const int k0 = kk * 16;
            uint32_t A[4][4];
#pragma unroll
            for (int mf = 0; mf < 4; mf++) {
                int r = wm * 64 + mf * 16 + gid;
                A[mf][0] = *reinterpret_cast<const uint32_t*>(pS + r * LDX + k0 + 2 * tg);
                A[mf][1] = *reinterpret_cast<const uint32_t*>(pS + (r + 8) * LDX + k0 + 2 * tg);
                A[mf][2] = *reinterpret_cast<const uint32_t*>(pS + r * LDX + k0 + 8 + 2 * tg);
                A[mf][3] = *reinterpret_cast<const uint32_t*>(pS + (r + 8) * LDX + k0 + 8 + 2 * tg);
            }
#pragma unroll
            for (int mf = 0; mf < 4; mf++)
#pragma unroll
                for (int nf = 0; nf < 4; nf++)
                    mma_f16(acc[mf][nf], A[mf], Bf[kk][nf]);
        }

        // E = fp16(exp(S - a_col)) -> direct half2 stores; accumulate column sums
        const int ibase = t * NCH;
#pragma unroll
        for (int mf = 0; mf < 4; mf++) {
            int r = wm * 64 + mf * 16 + gid;
#pragma unroll
            for (int nf = 0; nf < 4; nf++) {
                int c0 = wn * 32 + nf * 8 + 2 * tg;
                __half2 h01 = __floats2half2_rn(__expf(acc[mf][nf][0] - a_c[nf][0]),
                                                __expf(acc[mf][nf][1] - a_c[nf][1]));
                __half2 h23 = __floats2half2_rn(__expf(acc[mf][nf][2] - a_c[nf][0]),
                                                __expf(acc[mf][nf][3] - a_c[nf][1]));
                *reinterpret_cast<__half2*>(Eb + (size_t)(ibase + r) * T_DIM + j0 + c0)     = h01;
                *reinterpret_cast<__half2*>(Eb + (size_t)(ibase + r + 8) * T_DIM + j0 + c0) = h23;
                rs[nf][0] += __low2float(h01) + __low2float(h23);
                rs[nf][1] += __high2float(h01) + __high2float(h23);
            }
        }
    }

    // reduce rs over gid lanes (rows within warp), then across the 2 wm warps
#pragma unroll
    for (int nf = 0; nf < 4; nf++)
#pragma unroll
        for (int h = 0; h < 2; h++) {
            float v = rs[nf][h];
            v += __shfl_xor_sync(0xFFFFFFFFu, v, 4);
            v += __shfl_xor_sync(0xFFFFFFFFu, v, 8);
            v += __shfl_xor_sync(0xFFFFFFFFu, v, 16);
            rs[nf][h] = v;
        }
    __syncthreads();   // stream buffers dead; reuse SBUF[0] as reduction pad
    {
        float* red = reinterpret_cast<float*>(sm + SBUF[0]);  // 2 x 128 floats
        if (gid == 0) {
#pragma unroll
            for (int nf = 0; nf < 4; nf++) {
                int c0 = wn * 32 + nf * 8 + 2 * tg;
                red[wm * 128 + c0]     = rs[nf][0];
                red[wm * 128 + c0 + 1] = rs[nf][1];
            }
        }
        __syncthreads();
        if (tid < 128)
            g_r[b * T_DIM + j0 + tid] = 1.0f / (red[tid] + red[128 + tid]);
    }
}

// ---------------- k_out2: pure GEMM O[i][d] = sum_j E[i][j] Vt[d][j] --------
// 3-stage pipeline. smem: VT0 @0 | VT1 @17408 | VT2 @34816 |
//   E0 @52224 | E1 @87040 | E2 @121856 -> end 156672
__global__ void __launch_bounds__(256, 1) k_out2(float* __restrict__ out) {
    extern __shared__ char sm[];
    const uint32_t smb = smem_u32(sm);
    const int tid = threadIdx.x, w = tid >> 5, lane = tid & 31;
    const int wm = w >> 2, wn = w & 3;
    const int gid = lane >> 2, tg = lane & 3;
    const int b = blockIdx.y, i0 = blockIdx.x * 128;
    const __half* vt = g_vt + (size_t)b * D_DIM * T_DIM;
    const __half* Eb = g_E + (size_t)b * T_DIM * T_DIM + (size_t)i0 * T_DIM;
    float* ob = out + (size_t)b * D_DIM * T_DIM;

    const uint32_t VT[3] = {0, 17408, 34816};
    const uint32_t EB[3] = {52224, 87040, 121856};

    ld_vt(smb + VT[0], vt, tid);
    ld_e(smb + EB[0], Eb, tid);
    CP_COMMIT();
    ld_vt(smb + VT[1], vt + (size_t)NCH, tid);
    ld_e(smb + EB[1], Eb + (size_t)NCH, tid);
    CP_COMMIT();

    float accO[4][2][4];
#pragma unroll
    for (int mf = 0; mf < 4; mf++)
#pragma unroll
        for (int nf = 0; nf < 2; nf++)
#pragma unroll
            for (int q = 0; q < 4; q++) accO[mf][nf][q] = 0.f;

    for (int t = 0; t < NIT; t++) {
        if (t + 1 < NIT) CP_WAIT1(); else CP_WAIT0();
        __syncthreads();            // group t visible; buf[(t-1)%3] free
        if (t + 2 < NIT) {
            ld_vt(smb + VT[(t + 2) % 3], vt + (size_t)(t + 2) * NCH, tid);
            ld_e(smb + EB[(t + 2) % 3], Eb + (size_t)(t + 2) * NCH, tid);
            CP_COMMIT();
        }
        const __half* pE = reinterpret_cast<const __half*>(sm + EB[t % 3]);
        const __half* pT = reinterpret_cast<const __half*>(sm + VT[t % 3]);

#pragma unroll
        for (int kk = 0; kk < 8; kk++) {
            const int k0 = kk * 16;
            uint32_t A[4][4], Bf[2][2];
#pragma unroll
            for (int mf = 0; mf < 4; mf++) {
                int r = wm * 64 + mf * 16 + gid;
                A[mf][0] = *reinterpret_cast<const uint32_t*>(pE + r * LDE + k0 + 2 * tg);
                A[mf][1] = *reinterpret_cast<const uint32_t*>(pE + (r + 8) * LDE + k0 + 2 * tg);
                A[mf][2] = *reinterpret_cast<const uint32_t*>(pE + r * LDE + k0 + 8 + 2 * tg);
                A[mf][3] = *reinterpret_cast<const uint32_t*>(pE + (r + 8) * LDE + k0 + 8 + 2 * tg);
            }
#pragma unroll
            for (int nf = 0; nf < 2; nf++) {
                int cB = wn * 16 + nf * 8 + gid;
                Bf[nf][0] = *reinterpret_cast<const uint32_t*>(pT + cB * LDE + k0 + 2 * tg);
                Bf[nf][1] = *reinterpret_cast<const uint32_t*>(pT + cB * LDE + k0 + 8 + 2 * tg);
            }
#pragma unroll
            for (int mf = 0; mf < 4; mf++)
#pragma unroll
                for (int nf = 0; nf < 2; nf++)
                    mma_f16(accO[mf][nf], A[mf], Bf[nf]);
        }
    }

    // store transposed: out[b][d][i]
#pragma unroll
    for (int mf = 0; mf < 4; mf++)
#pragma unroll
        for (int nf = 0; nf < 2; nf++) {
            int r = i0 + wm * 64 + mf * 16 + gid;
            int c = wn * 16 + nf * 8 + 2 * tg;
            ob[(size_t)c * T_DIM + r]           = accO[mf][nf][0];
            ob[(size_t)(c + 1) * T_DIM + r]     = accO[mf][nf][1];
            ob[(size_t)c * T_DIM + r + 8]       = accO[mf][nf][2];
            ob[(size_t)(c + 1) * T_DIM + r + 8] = accO[mf][nf][3];
        }
}

// ---------------------------------------------------------------------------
extern "C" void kernel_launch(void* const* d_in, const int* in_sizes, int n_in,
                              void* d_out, int out_size) {
    const float* x = (const float*)d_in[0];
    float* out = (float*)d_out;

    const int smem_stats = 73728;
    const int smem_out   = 156672;
    cudaFuncSetAttribute(k_stats, cudaFuncAttributeMaxDynamicSharedMemorySize, smem_stats);
    cudaFuncSetAttribute(k_out2,  cudaFuncAttributeMaxDynamicSharedMemorySize, smem_out);

    k_prep<<<(B_DIM * T_DIM) / 16, 256>>>(x);
    k_stats<<<dim3(T_DIM / NCH, B_DIM), 256, smem_stats>>>();
    k_vt<<<dim3(T_DIM / 32, D_DIM / 32, B_DIM), 256>>>(x);
    k_out2<<<dim3(T_DIM / NCH, B_DIM), 256, smem_out>>>(out);
}